// round 5
// baseline (speedup 1.0000x reference)
#include <cuda_runtime.h>
#include <cstdint>

#define BLOCK   256
#define IT      4          // i-rows per thread (register blocking)
#define JS      256        // smem j-tile
#define NSLICES 37         // 8 i-chunks * 37 = 296 blocks = 2 * 148 SMs (perfect balance)

// Per-block partials + completion ticket (no cudaMalloc allowed).
__device__ float2 g_partials[1024];
__device__ int    g_ticket;          // zero-init; reset by last block every launch

__global__ __launch_bounds__(BLOCK)
void rank_loss_fused(const float* __restrict__ pred,
                     const float* __restrict__ targ,
                     const float* __restrict__ wgt,
                     const int*   __restrict__ ms_raw,
                     float* __restrict__ out,
                     int n, int jsLen)
{
    __shared__ float sT[JS], sP[JS], sW[JS];
    __shared__ float redT[BLOCK / 32], redC[BLOCK / 32];
    __shared__ bool  sIsLast;

    const int tid    = threadIdx.x;
    const int ichunk = blockIdx.x / NSLICES;
    const int jslice = blockIdx.x % NSLICES;

    // margin_scale: python int -> int32 most likely; tolerate f32 raw bits too.
    int raw = *ms_raw;
    float ms = (raw > -100000 && raw < 100000) ? (float)raw : __int_as_float(raw);
    const float c = 0.08f * ms;   // margin = c * clip(|td|, 0.1, 1.0)

    const float FNAN = __int_as_float(0x7fffffff);

    // Load this thread's IT i-rows (NaN target on padding -> never valid)
    float ti[IT], pi[IT], wi[IT];
    const int i0 = ichunk * (BLOCK * IT) + tid;
#pragma unroll
    for (int k = 0; k < IT; k++) {
        int i = i0 + k * BLOCK;
        if (i < n) { ti[k] = targ[i]; pi[k] = pred[i]; wi[k] = wgt[i]; }
        else       { ti[k] = FNAN;    pi[k] = 0.0f;    wi[k] = 0.0f;  }
    }

    float accV[IT], accWV[IT];
    int   acnt[IT];
#pragma unroll
    for (int k = 0; k < IT; k++) { accV[k] = 0.0f; accWV[k] = 0.0f; acnt[k] = 0; }

    const int jBeg = jslice * jsLen;
    const int jEnd = min(jBeg + jsLen, n);

    for (int jt = jBeg; jt < jEnd; jt += JS) {
        {
            int j = jt + tid;
            bool ok = (j < jEnd);
            sT[tid] = ok ? targ[j] : FNAN;
            sP[tid] = ok ? pred[j] : 0.0f;
            sW[tid] = ok ? wgt[j]  : 0.0f;
        }
        __syncthreads();

        const int tlen = min(JS, jEnd - jt);
#pragma unroll 4
        for (int j = 0; j < tlen; j++) {
            const float tj = sT[j];
            const float pj = sP[j];
            const float wj = sW[j];
#pragma unroll
            for (int k = 0; k < IT; k++) {
                float td    = ti[k] - tj;                      // FADD   (fma pipe)
                float ad    = fabsf(td);                       // |.| folds as modifier
                float mclip = fminf(fmaxf(ad, 0.1f), 1.0f);    // 2x FMNMX (fma)
                float pd    = pi[k] - pj;                      // FADD   (fma)
                // x = -sign(td)*pd : flip pd sign iff td>0 (one LOP3, alu)
                unsigned flip = (~__float_as_uint(td)) & 0x80000000u;
                float x     = __uint_as_float(__float_as_uint(pd) ^ flip);
                float v     = fmaf(c, mclip, x);               // FFMA   (fma)
                bool valid  = (ad >= 0.05f);                   // FSETP  (alu); NaN->false
                if (valid) acnt[k]++;                          // @P0 IADD3 (alu)
                if (valid && v > 0.0f) {                       // FSETP.AND (alu)
                    accV[k]  += v;                             // @P1 FADD (fma)
                    accWV[k]  = fmaf(wj, v, accWV[k]);         // @P1 FFMA (fma)
                }
            }
        }
        __syncthreads();
    }

    // (w_i + w_j) * v  summed ==  w_i * accV + accWV
    float tot = 0.0f, cnt = 0.0f;
#pragma unroll
    for (int k = 0; k < IT; k++) {
        tot += fmaf(wi[k], accV[k], accWV[k]);
        cnt += (float)acnt[k];
    }

#pragma unroll
    for (int off = 16; off > 0; off >>= 1) {
        tot += __shfl_down_sync(0xffffffffu, tot, off);
        cnt += __shfl_down_sync(0xffffffffu, cnt, off);
    }
    if ((tid & 31) == 0) { redT[tid >> 5] = tot; redC[tid >> 5] = cnt; }
    __syncthreads();

    if (tid < 32) {
        float t2 = (tid < BLOCK / 32) ? redT[tid] : 0.0f;
        float c2 = (tid < BLOCK / 32) ? redC[tid] : 0.0f;
#pragma unroll
        for (int off = 4; off > 0; off >>= 1) {
            t2 += __shfl_down_sync(0xffffffffu, t2, off);
            c2 += __shfl_down_sync(0xffffffffu, c2, off);
        }
        if (tid == 0) {
            g_partials[blockIdx.x] = make_float2(t2, c2);
            __threadfence();
            int old = atomicAdd(&g_ticket, 1);
            sIsLast = (old == (int)gridDim.x - 1);
        }
    }
    __syncthreads();

    // Last block to finish reduces all partials (deterministic order) in double.
    if (sIsLast) {
        __shared__ double sdT[BLOCK / 32], sdC[BLOCK / 32];
        double t = 0.0, cd = 0.0;
        for (int i = tid; i < (int)gridDim.x; i += BLOCK) {
            float2 p = g_partials[i];
            t  += (double)p.x;
            cd += (double)p.y;
        }
#pragma unroll
        for (int off = 16; off > 0; off >>= 1) {
            t  += __shfl_down_sync(0xffffffffu, t,  off);
            cd += __shfl_down_sync(0xffffffffu, cd, off);
        }
        if ((tid & 31) == 0) { sdT[tid >> 5] = t; sdC[tid >> 5] = cd; }
        __syncthreads();
        if (tid < 32) {
            double t2 = (tid < BLOCK / 32) ? sdT[tid] : 0.0;
            double c2 = (tid < BLOCK / 32) ? sdC[tid] : 0.0;
#pragma unroll
            for (int off = 4; off > 0; off >>= 1) {
                t2 += __shfl_down_sync(0xffffffffu, t2, off);
                c2 += __shfl_down_sync(0xffffffffu, c2, off);
            }
            if (tid == 0) {
                out[0] = (c2 > 0.0) ? (float)(0.5 * t2 / c2) : 0.0f;
                g_ticket = 0;              // reset for next (graph-replayed) launch
            }
        }
    }
}

extern "C" void kernel_launch(void* const* d_in, const int* in_sizes, int n_in,
                              void* d_out, int out_size)
{
    const float* pred = (const float*)d_in[0];
    const float* targ = (const float*)d_in[1];
    const float* wgt  = (const float*)d_in[2];
    const int*   msp  = (const int*)  d_in[3];
    float* out = (float*)d_out;

    int n = in_sizes[0];
    int numIChunks = (n + BLOCK * IT - 1) / (BLOCK * IT);   // 8 for n=8192
    int jsLen      = (n + NSLICES - 1) / NSLICES;           // 222
    int grid       = numIChunks * NSLICES;                  // 296 = 2*148

    rank_loss_fused<<<grid, BLOCK>>>(pred, targ, wgt, msp, out, n, jsLen);
}

// round 11
// speedup vs baseline: 1.4932x; 1.4932x over previous
#include <cuda_runtime.h>
#include <cstdint>

#define BLOCK   256
#define IT      4          // i-rows per thread (register blocking)
#define JS      256        // smem j-tile capacity
#define NSLICES 74         // 8 i-chunks * 74 = 592 blocks = 4 * 148 SMs (4 CTAs/SM)

// Per-block partials + completion ticket (no cudaMalloc allowed).
__device__ float2 g_partials[1024];
__device__ int    g_ticket;          // zero-init; reset by last block every launch

__global__ __launch_bounds__(BLOCK, 4)   // force 4 CTAs/SM residency (<=64 regs/thr)
void rank_loss_fused(const float* __restrict__ pred,
                     const float* __restrict__ targ,
                     const float* __restrict__ wgt,
                     const int*   __restrict__ ms_raw,
                     float* __restrict__ out,
                     int n, int jsLen)
{
    __shared__ float4 sJ[JS];                 // (targ, pred, wgt, pad) -> one LDS.128/j
    __shared__ float  redT[BLOCK / 32], redC[BLOCK / 32];
    __shared__ bool   sIsLast;

    const int tid    = threadIdx.x;
    const int ichunk = blockIdx.x / NSLICES;
    const int jslice = blockIdx.x % NSLICES;

    // margin_scale: python int -> int32 most likely; tolerate f32 raw bits too.
    int raw = *ms_raw;
    float ms = (raw > -100000 && raw < 100000) ? (float)raw : __int_as_float(raw);
    const float c = 0.08f * ms;   // margin = c * clip(|td|, 0.1, 1.0)

    const float FNAN = __int_as_float(0x7fffffff);

    // Load this thread's IT i-rows (NaN target on padding -> pair never valid)
    float ti[IT], pi[IT], wi[IT];
    const int i0 = ichunk * (BLOCK * IT) + tid;
#pragma unroll
    for (int k = 0; k < IT; k++) {
        int i = i0 + k * BLOCK;
        if (i < n) { ti[k] = targ[i]; pi[k] = pred[i]; wi[k] = wgt[i]; }
        else       { ti[k] = FNAN;    pi[k] = 0.0f;    wi[k] = 0.0f;  }
    }

    float accV[IT], accWV[IT];
    int   acnt[IT];
#pragma unroll
    for (int k = 0; k < IT; k++) { accV[k] = 0.0f; accWV[k] = 0.0f; acnt[k] = 0; }

    const int jBeg = jslice * jsLen;
    const int jEnd = min(jBeg + jsLen, n);

    for (int jt = jBeg; jt < jEnd; jt += JS) {
        {
            int j = jt + tid;
            bool ok = (j < jEnd);
            sJ[tid] = make_float4(ok ? targ[j] : FNAN,
                                  ok ? pred[j] : 0.0f,
                                  ok ? wgt[j]  : 0.0f,
                                  0.0f);
        }
        __syncthreads();

        const int tlen = min(JS, jEnd - jt);
#pragma unroll 8
        for (int j = 0; j < tlen; j++) {
            const float4 jv = sJ[j];          // LDS.128 broadcast (conflict-free)
            const float tj = jv.x;
            const float pj = jv.y;
            const float wj = jv.z;
#pragma unroll
            for (int k = 0; k < IT; k++) {
                float td    = ti[k] - tj;                      // FADD
                float ad    = fabsf(td);                       // |.| folds as modifier
                float mclip = fminf(fmaxf(ad, 0.1f), 1.0f);    // 2x FMNMX
                float pd    = pi[k] - pj;                      // FADD
                // x = pd ^ ((~td) & 0x80000000): single LOP3 (flip sign iff td>0)
                float x     = __uint_as_float(__float_as_uint(pd) ^
                                ((~__float_as_uint(td)) & 0x80000000u));
                float viol  = fmaxf(fmaf(c, mclip, x), 0.0f);  // FFMA + FMNMX
                if (ad >= 0.05f) {          // single FSETP; NaN -> false masks padding
                    accV[k]  += viol;                          // @P FADD
                    accWV[k]  = fmaf(wj, viol, accWV[k]);      // @P FFMA
                    acnt[k]  += 1;                             // @P IADD3
                }
            }
        }
        __syncthreads();
    }

    // (w_i + w_j) * v  summed ==  w_i * accV + accWV
    float tot = 0.0f, cnt = 0.0f;
#pragma unroll
    for (int k = 0; k < IT; k++) {
        tot += fmaf(wi[k], accV[k], accWV[k]);
        cnt += (float)acnt[k];
    }

#pragma unroll
    for (int off = 16; off > 0; off >>= 1) {
        tot += __shfl_down_sync(0xffffffffu, tot, off);
        cnt += __shfl_down_sync(0xffffffffu, cnt, off);
    }
    if ((tid & 31) == 0) { redT[tid >> 5] = tot; redC[tid >> 5] = cnt; }
    __syncthreads();

    if (tid < 32) {
        float t2 = (tid < BLOCK / 32) ? redT[tid] : 0.0f;
        float c2 = (tid < BLOCK / 32) ? redC[tid] : 0.0f;
#pragma unroll
        for (int off = 4; off > 0; off >>= 1) {
            t2 += __shfl_down_sync(0xffffffffu, t2, off);
            c2 += __shfl_down_sync(0xffffffffu, c2, off);
        }
        if (tid == 0) {
            g_partials[blockIdx.x] = make_float2(t2, c2);
            __threadfence();
            int old = atomicAdd(&g_ticket, 1);
            sIsLast = (old == (int)gridDim.x - 1);
        }
    }
    __syncthreads();

    // Last block to finish reduces all partials (deterministic order) in double.
    if (sIsLast) {
        __shared__ double sdT[BLOCK / 32], sdC[BLOCK / 32];
        double t = 0.0, cd = 0.0;
        for (int i = tid; i < (int)gridDim.x; i += BLOCK) {
            float2 p = g_partials[i];
            t  += (double)p.x;
            cd += (double)p.y;
        }
#pragma unroll
        for (int off = 16; off > 0; off >>= 1) {
            t  += __shfl_down_sync(0xffffffffu, t,  off);
            cd += __shfl_down_sync(0xffffffffu, cd, off);
        }
        if ((tid & 31) == 0) { sdT[tid >> 5] = t; sdC[tid >> 5] = cd; }
        __syncthreads();
        if (tid < 32) {
            double t2 = (tid < BLOCK / 32) ? sdT[tid] : 0.0;
            double c2 = (tid < BLOCK / 32) ? sdC[tid] : 0.0;
#pragma unroll
            for (int off = 4; off > 0; off >>= 1) {
                t2 += __shfl_down_sync(0xffffffffu, t2, off);
                c2 += __shfl_down_sync(0xffffffffu, c2, off);
            }
            if (tid == 0) {
                out[0] = (c2 > 0.0) ? (float)(0.5 * t2 / c2) : 0.0f;
                g_ticket = 0;              // reset for next (graph-replayed) launch
            }
        }
    }
}

extern "C" void kernel_launch(void* const* d_in, const int* in_sizes, int n_in,
                              void* d_out, int out_size)
{
    const float* pred = (const float*)d_in[0];
    const float* targ = (const float*)d_in[1];
    const float* wgt  = (const float*)d_in[2];
    const int*   msp  = (const int*)  d_in[3];
    float* out = (float*)d_out;

    int n = in_sizes[0];
    int numIChunks = (n + BLOCK * IT - 1) / (BLOCK * IT);   // 8 for n=8192
    int jsLen      = (n + NSLICES - 1) / NSLICES;           // 111
    int grid       = numIChunks * NSLICES;                  // 592 = 4*148

    rank_loss_fused<<<grid, BLOCK>>>(pred, targ, wgt, msp, out, n, jsLen);
}